// round 4
// baseline (speedup 1.0000x reference)
#include <cuda_runtime.h>
#include <cuda_bf16.h>
#include <cstdint>

#define BATCH 8
#define NPTS  4096
#define DDIM  512
#define NT    32            // 4096/128 row tiles
#define GRID_X 272          // sum over ti of ceil((NT-ti)/2)
#define BK    64
#define NCHUNK 8            // DDIM/BK
#define TILEB 16384         // one 128x64 bf16 tile
#define STAGE_BYTES (3*TILEB)   // A + B0 + B1 = 48KB
#define NSTAGE 3
#define SMEM_DYN (NSTAGE*STAGE_BYTES + 1024)

__device__ __nv_bfloat16 g_xb[(size_t)BATCH * NPTS * DDIM];
__device__ float g_sq[BATCH * NPTS];
__device__ float g_inv[BATCH * NPTS];

// ---------------------------------------------------------------- prep ----
__global__ void prep_kernel(const float* __restrict__ emb) {
    int row = blockIdx.x;               // b*NPTS + n
    int tid = threadIdx.x;              // 128 threads
    float4 v = ((const float4*)(emb + (size_t)row * DDIM))[tid];

    float s = fmaf(v.x, v.x, fmaf(v.y, v.y, fmaf(v.z, v.z, v.w * v.w)));
    __shared__ float red[4];
#pragma unroll
    for (int o = 16; o > 0; o >>= 1) s += __shfl_down_sync(0xffffffffu, s, o);
    if ((tid & 31) == 0) red[tid >> 5] = s;
    __syncthreads();
    float tot = red[0] + red[1] + red[2] + red[3];

    if (sqrtf(tot) >= 1.f) {            // __proj (faithful; won't trigger here)
        float invn = rsqrtf(tot);
        v.x = v.x * invn - 1e-5f; v.y = v.y * invn - 1e-5f;
        v.z = v.z * invn - 1e-5f; v.w = v.w * invn - 1e-5f;
        float s2 = fmaf(v.x, v.x, fmaf(v.y, v.y, fmaf(v.z, v.z, v.w * v.w)));
#pragma unroll
        for (int o = 16; o > 0; o >>= 1) s2 += __shfl_down_sync(0xffffffffu, s2, o);
        __syncthreads();
        if ((tid & 31) == 0) red[tid >> 5] = s2;
        __syncthreads();
        tot = red[0] + red[1] + red[2] + red[3];
    }

    __nv_bfloat162 p0 = __floats2bfloat162_rn(v.x, v.y);
    __nv_bfloat162 p1 = __floats2bfloat162_rn(v.z, v.w);
    uint2 u;
    u.x = *(uint32_t*)&p0;
    u.y = *(uint32_t*)&p1;
    ((uint2*)(g_xb + (size_t)row * DDIM))[tid] = u;
    if (tid == 0) {
        g_sq[row]  = tot;
        g_inv[row] = 1.f / (1.f - tot);
    }
}

// ------------------------------------------------------------- helpers ----
__device__ __forceinline__ void cp_async16(uint32_t dst, const void* src) {
    asm volatile("cp.async.cg.shared.global [%0], [%1], 16;\n" :: "r"(dst), "l"(src));
}
__device__ __forceinline__ void cp_commit() {
    asm volatile("cp.async.commit_group;\n" ::);
}
template <int N>
__device__ __forceinline__ void cp_wait() {
    asm volatile("cp.async.wait_group %0;\n" :: "n"(N));
}
__device__ __forceinline__ void ldsm_x4(uint32_t& r0, uint32_t& r1,
                                        uint32_t& r2, uint32_t& r3, uint32_t a) {
    asm volatile("ldmatrix.sync.aligned.m8n8.x4.shared.b16 {%0,%1,%2,%3}, [%4];\n"
                 : "=r"(r0), "=r"(r1), "=r"(r2), "=r"(r3) : "r"(a));
}

__device__ __forceinline__ float hyp_dist(float gv, float sa, float sb,
                                          float ia, float ib, bool diag) {
    float d2 = fmaxf(sa + sb - 2.f * gv, 0.f);
    float dn;
    asm("sqrt.approx.f32 %0, %1;" : "=f"(dn) : "f"(d2));
    float t = 2.f * dn * ia * ib;           // arg = 1 + t
    float w;
    asm("sqrt.approx.f32 %0, %1;" : "=f"(w) : "f"(t * (t + 2.f)));  // sqrt(arg^2-1)
    float arg = 1.f + t + w;
    float lg;
    asm("lg2.approx.f32 %0, %1;" : "=f"(lg) : "f"(arg));
    return (t > 0.f && !diag) ? lg * 0.69314718055994531f : 0.f;
}

// ---------------------------------------------------------------- gemm ----
__global__ void __launch_bounds__(256, 1)
gram_dist_kernel(float* __restrict__ out) {
    extern __shared__ char smem_raw[];
    __shared__ float s_sqi[128], s_invi[128], s_sqj[256], s_invj[256];

    const int b  = blockIdx.y;
    const int bN = b * NPTS;

    // block index -> (ti, tj0); block covers j-tiles tj0 and tj0+1 (if valid)
    int p = blockIdx.x, ti = 0;
    while (p >= ((NT + 1 - ti) >> 1)) { p -= (NT + 1 - ti) >> 1; ++ti; }
    const int tj0    = ti + 2 * p;
    const bool valid1 = (tj0 + 1) < NT;
    const bool alias0 = (tj0 == ti);            // B0 == A tile
    const int tjL    = valid1 ? tj0 + 1 : tj0;  // clamped load row for B1

    const int tid  = threadIdx.x;
    const int warp = tid >> 5;
    const int lane = tid & 31;
    const int g  = lane >> 2;           // 0..7
    const int t2 = (lane & 3) * 2;      // 0,2,4,6
    const int wm = warp & 1;            // row half (64)
    const int wn = warp >> 1;           // col quarter (64 of 256)

    const uint32_t base_gen = (uint32_t)__cvta_generic_to_shared(smem_raw);
    const uint32_t sbase0   = (base_gen + 1023u) & ~1023u;
    float* stageT = (float*)(smem_raw + (sbase0 - base_gen));

    // epilogue params (j-cols 0..255 are contiguous rows tj0*128 ..)
    if (tid < 128) {
        s_sqi[tid]  = g_sq[bN + ti * 128 + tid];
        s_invi[tid] = g_inv[bN + ti * 128 + tid];
    }
    {
        int jr = tj0 * 128 + tid;
        if (jr > NPTS - 1) jr = NPTS - 1;       // clamp (invalid subtile 1)
        s_sqj[tid]  = g_sq[bN + jr];
        s_invj[tid] = g_inv[bN + jr];
    }

    // --- loader (SW-style XOR swizzle per 128B row) ---
    const size_t rowA  = (size_t)(bN + ti  * 128) * DDIM;
    const size_t rowB0 = (size_t)(bN + tj0 * 128) * DDIM;
    const size_t rowB1 = (size_t)(bN + tjL * 128) * DDIM;
    size_t   gb[3];
    uint32_t so[3];
    int ntile;
    if (alias0) { gb[0] = rowA; so[0] = 0; gb[1] = rowB1; so[1] = 2 * TILEB; ntile = 2; }
    else {
        gb[0] = rowA;  so[0] = 0;
        gb[1] = rowB0; so[1] = TILEB;
        gb[2] = rowB1; so[2] = 2 * TILEB;
        ntile = 3;
    }
    auto load_stage = [&](int s, int k0) {
        uint32_t sb = sbase0 + s * STAGE_BYTES;
        const int nIt = 4 * ntile;
        for (int i = 0; i < nIt; ++i) {
            int chunk = i * 256 + tid;
            int tile  = chunk >> 10;
            int cid   = chunk & 1023;
            int row   = cid >> 3;
            int c     = cid & 7;
            const __nv_bfloat16* src = g_xb + gb[tile] + (size_t)row * DDIM + k0 + c * 8;
            uint32_t dst = sb + so[tile] + row * 128 + ((c ^ (row & 7)) << 4);
            cp_async16(dst, src);
        }
    };

    // fragment geometry
    const int swz = lane & 7;
    const int dcA = lane >> 4;
    const int dcB = (lane >> 3) & 1;
    uint32_t aByte[4], bByte[4];
#pragma unroll
    for (int mt = 0; mt < 4; ++mt)
        aByte[mt] = (uint32_t)((wm * 64 + mt * 16 + (lane & 15)) * 128);
    const uint32_t bTile = (wn >= 2) ? (uint32_t)(2 * TILEB)
                                     : (alias0 ? 0u : (uint32_t)TILEB);
    const int lcb = (wn & 1) * 64;      // local col base within its 128-col B tile
#pragma unroll
    for (int pp = 0; pp < 4; ++pp)
        bByte[pp] = bTile + (uint32_t)((lcb + pp * 16 + (lane & 7) + ((lane >> 4) << 3)) * 128);

    float acc[4][8][4];
#pragma unroll
    for (int a = 0; a < 4; ++a)
#pragma unroll
        for (int c = 0; c < 8; ++c)
#pragma unroll
            for (int r = 0; r < 4; ++r) acc[a][c][r] = 0.f;

    load_stage(0, 0);  cp_commit();
    load_stage(1, BK); cp_commit();

    for (int kb = 0; kb < NCHUNK; ++kb) {
        if (kb < NCHUNK - 1) cp_wait<1>(); else cp_wait<0>();
        __syncthreads();
        if (kb + 2 < NCHUNK) { load_stage((kb + 2) % NSTAGE, (kb + 2) * BK); cp_commit(); }

        uint32_t sb = sbase0 + (kb % NSTAGE) * STAGE_BYTES;
#pragma unroll
        for (int kk = 0; kk < BK; kk += 16) {
            const int c0 = kk >> 3;
            const uint32_t cA = (uint32_t)(((c0 | dcA) ^ swz) << 4);
            const uint32_t cB = (uint32_t)(((c0 | dcB) ^ swz) << 4);
            uint32_t afr[4][4], bfr[8][2];
#pragma unroll
            for (int mt = 0; mt < 4; ++mt)
                ldsm_x4(afr[mt][0], afr[mt][1], afr[mt][2], afr[mt][3],
                        sb + aByte[mt] + cA);
#pragma unroll
            for (int pp = 0; pp < 4; ++pp)
                ldsm_x4(bfr[2 * pp][0], bfr[2 * pp][1], bfr[2 * pp + 1][0], bfr[2 * pp + 1][1],
                        sb + bByte[pp] + cB);
#pragma unroll
            for (int mt = 0; mt < 4; ++mt)
#pragma unroll
                for (int nt = 0; nt < 8; ++nt) {
                    asm volatile(
                        "mma.sync.aligned.m16n8k16.row.col.f32.bf16.bf16.f32 "
                        "{%0,%1,%2,%3}, {%4,%5,%6,%7}, {%8,%9}, {%0,%1,%2,%3};\n"
                        : "+f"(acc[mt][nt][0]), "+f"(acc[mt][nt][1]),
                          "+f"(acc[mt][nt][2]), "+f"(acc[mt][nt][3])
                        : "r"(afr[mt][0]), "r"(afr[mt][1]),
                          "r"(afr[mt][2]), "r"(afr[mt][3]),
                          "r"(bfr[nt][0]), "r"(bfr[nt][1]));
                }
        }
    }

    // ---------------- epilogue pass 1: distances + direct stores -----------
    float* outB = out + (size_t)b * NPTS * NPTS;
    const int gi0 = ti * 128;

#pragma unroll
    for (int mt = 0; mt < 4; ++mt) {
        int rl = wm * 64 + mt * 16 + g;
#pragma unroll
        for (int nt = 0; nt < 8; ++nt) {
            int cl = wn * 64 + nt * 8 + t2;     // 0..255
            int s  = cl >> 7;
            int lcol = cl & 127;
            int tjs = tj0 + s;
            bool okst = (s == 0) || valid1;
            bool dg   = (tjs == ti);
            float sb0 = s_sqj[cl],     ib0 = s_invj[cl];
            float sb1 = s_sqj[cl + 1], ib1 = s_invj[cl + 1];
            size_t gjb = (size_t)tjs * 128 + lcol;
#pragma unroll
            for (int h = 0; h < 2; ++h) {
                int rr = rl + h * 8;
                float sa = s_sqi[rr], ia = s_invi[rr];
                float v0 = hyp_dist(acc[mt][nt][h * 2 + 0], sa, sb0, ia, ib0, dg && (rr == lcol));
                float v1 = hyp_dist(acc[mt][nt][h * 2 + 1], sa, sb1, ia, ib1, dg && (rr == lcol + 1));
                acc[mt][nt][h * 2 + 0] = v0;
                acc[mt][nt][h * 2 + 1] = v1;
                if (okst) {
                    float2 pk; pk.x = v0; pk.y = v1;
                    *(float2*)(outB + (size_t)(gi0 + rr) * NPTS + gjb) = pk;
                }
            }
        }
    }

    // ---------------- epilogue pass 2: mirror via smem staging -------------
    __syncthreads();                    // all smem gemm reads complete
    for (int jc = 0; jc < 8; ++jc) {    // 8 groups of 32 cols over 256
        int s   = jc >> 2;
        int tjs = tj0 + s;
        bool mir = (tjs > ti) && ((s == 0) || valid1);
        if (mir && wn == (jc >> 1)) {
            int nt0 = (jc & 1) * 4;
#pragma unroll
            for (int mt = 0; mt < 4; ++mt)
#pragma unroll
                for (int q = 0; q < 4; ++q) {
                    int nt = nt0 + q;
                    int cg = nt * 8 + t2 - (jc & 1) * 32;   // 0..31 (pairs)
#pragma unroll
                    for (int h = 0; h < 2; ++h) {
                        int r = wm * 64 + mt * 16 + g + h * 8;
                        stageT[cg * 132 + r]       = acc[mt][nt][h * 2 + 0];
                        stageT[(cg + 1) * 132 + r] = acc[mt][nt][h * 2 + 1];
                    }
                }
        }
        __syncthreads();
        if (mir) {
            int gj0 = tjs * 128 + (jc & 3) * 32;
#pragma unroll
            for (int it = 0; it < 4; ++it) {
                int idx = it * 256 + tid;
                int row = idx >> 5;          // 0..31
                int q   = idx & 31;
                float4 v = *(const float4*)&stageT[row * 132 + q * 4];
                *(float4*)(outB + (size_t)(gj0 + row) * NPTS + gi0 + q * 4) = v;
            }
        }
        __syncthreads();
    }
}

// -------------------------------------------------------------- launch ----
extern "C" void kernel_launch(void* const* d_in, const int* in_sizes, int n_in,
                              void* d_out, int out_size) {
    const float* emb = (const float*)d_in[0];
    float* out = (float*)d_out;

    prep_kernel<<<BATCH * NPTS, 128>>>(emb);

    cudaFuncSetAttribute(gram_dist_kernel,
                         cudaFuncAttributeMaxDynamicSharedMemorySize, SMEM_DYN);
    dim3 grid(GRID_X, BATCH);
    gram_dist_kernel<<<grid, 256, SMEM_DYN>>>(out);
}

// round 5
// speedup vs baseline: 4.0091x; 4.0091x over previous
#include <cuda_runtime.h>
#include <cuda_bf16.h>
#include <cstdint>

#define BATCH 8
#define NPTS  4096
#define DDIM  512
#define NT    32            // 4096/128 row tiles
#define GRID_X 272          // sum over ti of ceil((NT-ti)/2)
#define BK    64
#define NCHUNK 8            // DDIM/BK
#define STAGE_BYTES 49152   // A(128x64) 16KB + B(256x64) 32KB
#define NSTAGE 3
#define SMEM_DYN (NSTAGE*STAGE_BYTES + 1024)

__device__ __nv_bfloat16 g_xb[(size_t)BATCH * NPTS * DDIM];
__device__ float g_sq[BATCH * NPTS];
__device__ float g_inv[BATCH * NPTS];

// ---------------------------------------------------------------- prep ----
__global__ void prep_kernel(const float* __restrict__ emb) {
    int row = blockIdx.x;               // b*NPTS + n
    int tid = threadIdx.x;              // 128 threads
    float4 v = ((const float4*)(emb + (size_t)row * DDIM))[tid];

    float s = fmaf(v.x, v.x, fmaf(v.y, v.y, fmaf(v.z, v.z, v.w * v.w)));
    __shared__ float red[4];
#pragma unroll
    for (int o = 16; o > 0; o >>= 1) s += __shfl_down_sync(0xffffffffu, s, o);
    if ((tid & 31) == 0) red[tid >> 5] = s;
    __syncthreads();
    float tot = red[0] + red[1] + red[2] + red[3];

    if (sqrtf(tot) >= 1.f) {            // __proj (faithful; won't trigger here)
        float invn = rsqrtf(tot);
        v.x = v.x * invn - 1e-5f; v.y = v.y * invn - 1e-5f;
        v.z = v.z * invn - 1e-5f; v.w = v.w * invn - 1e-5f;
        float s2 = fmaf(v.x, v.x, fmaf(v.y, v.y, fmaf(v.z, v.z, v.w * v.w)));
#pragma unroll
        for (int o = 16; o > 0; o >>= 1) s2 += __shfl_down_sync(0xffffffffu, s2, o);
        __syncthreads();
        if ((tid & 31) == 0) red[tid >> 5] = s2;
        __syncthreads();
        tot = red[0] + red[1] + red[2] + red[3];
    }

    __nv_bfloat162 p0 = __floats2bfloat162_rn(v.x, v.y);
    __nv_bfloat162 p1 = __floats2bfloat162_rn(v.z, v.w);
    uint2 u;
    u.x = *(uint32_t*)&p0;
    u.y = *(uint32_t*)&p1;
    ((uint2*)(g_xb + (size_t)row * DDIM))[tid] = u;
    if (tid == 0) {
        g_sq[row]  = tot;
        g_inv[row] = 1.f / (1.f - tot);
    }
}

// ------------------------------------------------------------- helpers ----
__device__ __forceinline__ void cp_async16(uint32_t dst, const void* src) {
    asm volatile("cp.async.cg.shared.global [%0], [%1], 16;\n" :: "r"(dst), "l"(src));
}
__device__ __forceinline__ void cp_commit() {
    asm volatile("cp.async.commit_group;\n" ::);
}
template <int N>
__device__ __forceinline__ void cp_wait() {
    asm volatile("cp.async.wait_group %0;\n" :: "n"(N));
}
__device__ __forceinline__ void ldsm_x4(uint32_t& r0, uint32_t& r1,
                                        uint32_t& r2, uint32_t& r3, uint32_t a) {
    asm volatile("ldmatrix.sync.aligned.m8n8.x4.shared.b16 {%0,%1,%2,%3}, [%4];\n"
                 : "=r"(r0), "=r"(r1), "=r"(r2), "=r"(r3) : "r"(a));
}

__device__ __forceinline__ float hyp_dist(float gv, float sa, float sb,
                                          float ia, float ib, bool diag) {
    float d2 = fmaxf(sa + sb - 2.f * gv, 0.f);
    float dn;
    asm("sqrt.approx.f32 %0, %1;" : "=f"(dn) : "f"(d2));
    float t = 2.f * dn * ia * ib;           // arg = 1 + t
    float w;
    asm("sqrt.approx.f32 %0, %1;" : "=f"(w) : "f"(t * (t + 2.f)));  // sqrt(arg^2-1)
    float arg = 1.f + t + w;
    float lg;
    asm("lg2.approx.f32 %0, %1;" : "=f"(lg) : "f"(arg));
    return (t > 0.f && !diag) ? lg * 0.69314718055994531f : 0.f;
}

// ---------------------------------------------------------------- gemm ----
__global__ void __launch_bounds__(256, 1)
gram_dist_kernel(float* __restrict__ out) {
    extern __shared__ char smem_raw[];
    __shared__ float s_sqi[128], s_invi[128], s_sqj[256], s_invj[256];

    const int b  = blockIdx.y;
    const int bN = b * NPTS;

    // block -> (ti, tj0); covers j-tiles tj0, tj0+1
    int p = blockIdx.x, ti = 0;
    while (p >= ((NT + 1 - ti) >> 1)) { p -= (NT + 1 - ti) >> 1; ++ti; }
    const int tj0 = ti + 2 * p;
    const bool valid1 = (tj0 + 1) < NT;

    const int tid  = threadIdx.x;
    const int warp = tid >> 5;
    const int lane = tid & 31;
    const int g  = lane >> 2;
    const int t2 = (lane & 3) * 2;
    const int wm = warp & 1;            // m half (64 rows)
    const int wn = warp >> 1;           // n quarter (64 of 256 cols)

    const uint32_t base_gen = (uint32_t)__cvta_generic_to_shared(smem_raw);
    const uint32_t sbase0   = (base_gen + 1023u) & ~1023u;
    float* stageT = (float*)(smem_raw + (sbase0 - base_gen));

    // epilogue params
    if (tid < 128) {
        s_sqi[tid]  = g_sq[bN + ti * 128 + tid];
        s_invi[tid] = g_inv[bN + ti * 128 + tid];
    }
    {
        int jr = tj0 * 128 + tid;
        if (jr >= NPTS) jr -= 128;
        s_sqj[tid]  = g_sq[bN + jr];
        s_invj[tid] = g_inv[bN + jr];
    }

    // --- loader: rows 0..127 = A (ti), 128..383 = B (tj0..tj0+1) ---
    auto load_stage = [&](int s, int k0) {
        uint32_t sb = sbase0 + (uint32_t)s * STAGE_BYTES;
#pragma unroll
        for (int i = 0; i < 12; ++i) {
            int chunk = i * 256 + tid;
            int row = chunk >> 3;          // 0..383
            int c   = chunk & 7;
            int gr  = (row < 128) ? (ti * 128 + row) : (tj0 * 128 + row - 128);
            if (gr >= NPTS) gr -= 128;     // clamp invalid B1 rows
            const __nv_bfloat16* src = g_xb + (size_t)(bN + gr) * DDIM + (k0 + c * 8);
            uint32_t dst = sb + (uint32_t)(row * 128 + (((c ^ row) & 7) << 4));
            cp_async16(dst, src);
        }
    };

    // fragment geometry
    const int swz = lane & 7;
    const int dcA = lane >> 4;
    const int dcB = (lane >> 3) & 1;
    uint32_t aByte[4], bByte[4];
#pragma unroll
    for (int mt = 0; mt < 4; ++mt)
        aByte[mt] = (uint32_t)((wm * 64 + mt * 16 + (lane & 15)) * 128);
#pragma unroll
    for (int pp = 0; pp < 4; ++pp)
        bByte[pp] = (uint32_t)(16384 + (wn * 64 + pp * 16 + (lane & 7) + ((lane >> 4) << 3)) * 128);

    float acc[4][8][4];
#pragma unroll
    for (int a = 0; a < 4; ++a)
#pragma unroll
        for (int c = 0; c < 8; ++c)
#pragma unroll
            for (int r = 0; r < 4; ++r) acc[a][c][r] = 0.f;

    load_stage(0, 0);  cp_commit();
    load_stage(1, BK); cp_commit();

    for (int kb = 0; kb < NCHUNK; ++kb) {
        if (kb + 2 < NCHUNK) cp_wait<1>(); else cp_wait<0>();
        __syncthreads();
        if (kb + 2 < NCHUNK) { load_stage((kb + 2) % NSTAGE, (kb + 2) * BK); cp_commit(); }

        uint32_t sb = sbase0 + (uint32_t)(kb % NSTAGE) * STAGE_BYTES;
#pragma unroll
        for (int kk = 0; kk < BK; kk += 16) {
            const int c0 = kk >> 3;
            const uint32_t cA = (uint32_t)(((c0 | dcA) ^ swz) << 4);
            const uint32_t cB = (uint32_t)(((c0 | dcB) ^ swz) << 4);
            uint32_t afr[4][4], bfr[8][2];
#pragma unroll
            for (int mt = 0; mt < 4; ++mt)
                ldsm_x4(afr[mt][0], afr[mt][1], afr[mt][2], afr[mt][3],
                        sb + aByte[mt] + cA);
#pragma unroll
            for (int pp = 0; pp < 4; ++pp)
                ldsm_x4(bfr[2 * pp][0], bfr[2 * pp][1], bfr[2 * pp + 1][0], bfr[2 * pp + 1][1],
                        sb + bByte[pp] + cB);
#pragma unroll
            for (int mt = 0; mt < 4; ++mt)
#pragma unroll
                for (int nt = 0; nt < 8; ++nt) {
                    asm volatile(
                        "mma.sync.aligned.m16n8k16.row.col.f32.bf16.bf16.f32 "
                        "{%0,%1,%2,%3}, {%4,%5,%6,%7}, {%8,%9}, {%0,%1,%2,%3};\n"
                        : "+f"(acc[mt][nt][0]), "+f"(acc[mt][nt][1]),
                          "+f"(acc[mt][nt][2]), "+f"(acc[mt][nt][3])
                        : "r"(afr[mt][0]), "r"(afr[mt][1]),
                          "r"(afr[mt][2]), "r"(afr[mt][3]),
                          "r"(bfr[nt][0]), "r"(bfr[nt][1]));
                }
        }
    }

    // ---------------- epilogue 1: distances + direct stores ---------------
    float* outB = out + (size_t)b * NPTS * NPTS;
    const uint32_t gi0 = (uint32_t)(ti * 128);
    const uint32_t gj0 = (uint32_t)(tj0 * 128);

#pragma unroll
    for (int mt = 0; mt < 4; ++mt) {
        const int rl = wm * 64 + mt * 16 + g;
#pragma unroll
        for (int nt = 0; nt < 8; ++nt) {
            const int cl = wn * 64 + nt * 8 + t2;     // 0..255
            const bool okst = (cl < 128) || valid1;
            const uint32_t gj = gj0 + (uint32_t)cl;
            const float sb0 = s_sqj[cl],     ib0 = s_invj[cl];
            const float sb1 = s_sqj[cl + 1], ib1 = s_invj[cl + 1];
#pragma unroll
            for (int h = 0; h < 2; ++h) {
                const uint32_t gi = gi0 + (uint32_t)(rl + h * 8);
                const float sa = s_sqi[rl + h * 8], ia = s_invi[rl + h * 8];
                float v0 = hyp_dist(acc[mt][nt][h * 2 + 0], sa, sb0, ia, ib0, gi == gj);
                float v1 = hyp_dist(acc[mt][nt][h * 2 + 1], sa, sb1, ia, ib1, gi == gj + 1u);
                acc[mt][nt][h * 2 + 0] = v0;
                acc[mt][nt][h * 2 + 1] = v1;
                if (okst) {
                    float2 pk; pk.x = v0; pk.y = v1;
                    *(float2*)(outB + (gi * (uint32_t)NPTS + gj)) = pk;
                }
            }
        }
    }

    // ---------------- epilogue 2: mirror via smem (4 groups x 2 passes) ----
    __syncthreads();                    // stage smem free for reuse
    const int itw = wn >> 1;            // pass in which this warp writes
    const int qb0 = (wn & 1) * 2;

    for (int it2 = 0; it2 < 2; ++it2) {
        if (it2 == itw) {
#pragma unroll
            for (int mt = 0; mt < 4; ++mt)
#pragma unroll
                for (int nt = 0; nt < 8; ++nt) {
                    const int qb = qb0 + (nt >> 2);
                    const int c  = (nt & 3) * 8 + t2;
                    float* tp = stageT + qb * 4224 + c * 132;
#pragma unroll
                    for (int h = 0; h < 2; ++h) {
                        const int r = wm * 64 + mt * 16 + g + h * 8;
                        tp[r]       = acc[mt][nt][h * 2 + 0];
                        tp[132 + r] = acc[mt][nt][h * 2 + 1];
                    }
                }
        }
        __syncthreads();
#pragma unroll
        for (int i2 = 0; i2 < 16; ++i2) {
            const int idx = i2 * 256 + tid;
            const int qb  = idx >> 10;
            const int jc  = it2 * 4 + qb;
            const int tjs = tj0 + (jc >> 2);
            if ((tjs > ti) && ((jc < 4) || valid1)) {
                const int rem  = idx & 1023;
                const int rowq = rem >> 5;
                const int q4   = rem & 31;
                float4 v = *(const float4*)(stageT + qb * 4224 + rowq * 132 + q4 * 4);
                const uint32_t gj = (uint32_t)(tjs * 128 + (jc & 3) * 32 + rowq);
                *(float4*)(outB + (gj * (uint32_t)NPTS + gi0 + (uint32_t)(q4 * 4))) = v;
            }
        }
        __syncthreads();
    }
}

// -------------------------------------------------------------- launch ----
extern "C" void kernel_launch(void* const* d_in, const int* in_sizes, int n_in,
                              void* d_out, int out_size) {
    const float* emb = (const float*)d_in[0];
    float* out = (float*)d_out;

    prep_kernel<<<BATCH * NPTS, 128>>>(emb);

    cudaFuncSetAttribute(gram_dist_kernel,
                         cudaFuncAttributeMaxDynamicSharedMemorySize, SMEM_DYN);
    dim3 grid(GRID_X, BATCH);
    gram_dist_kernel<<<grid, 256, SMEM_DYN>>>(out);
}

// round 6
// speedup vs baseline: 4.4860x; 1.1190x over previous
#include <cuda_runtime.h>
#include <cuda_bf16.h>
#include <cstdint>

#define BATCH 8
#define NPTS  4096
#define DDIM  512
#define NT    32            // 4096/128 row tiles
#define GRID_X 272          // sum over ti of ceil((NT-ti)/2)
#define BK    64
#define NCHUNK 8            // DDIM/BK
#define STAGE_BYTES 49152   // A(128x64) 16KB + B(256x64) 32KB
#define NSTAGE 4
#define SMEM_DYN (NSTAGE*STAGE_BYTES + 1024)   // 192KB + slack

__device__ __nv_bfloat16 g_xb[(size_t)BATCH * NPTS * DDIM];
__device__ float g_sq[BATCH * NPTS];
__device__ float g_inv[BATCH * NPTS];

// ---------------------------------------------------------------- prep ----
__global__ void prep_kernel(const float* __restrict__ emb) {
    int row = blockIdx.x;               // b*NPTS + n
    int tid = threadIdx.x;              // 128 threads
    float4 v = ((const float4*)(emb + (size_t)row * DDIM))[tid];

    float s = fmaf(v.x, v.x, fmaf(v.y, v.y, fmaf(v.z, v.z, v.w * v.w)));
    __shared__ float red[4];
#pragma unroll
    for (int o = 16; o > 0; o >>= 1) s += __shfl_down_sync(0xffffffffu, s, o);
    if ((tid & 31) == 0) red[tid >> 5] = s;
    __syncthreads();
    float tot = red[0] + red[1] + red[2] + red[3];

    if (sqrtf(tot) >= 1.f) {            // __proj (faithful; won't trigger here)
        float invn = rsqrtf(tot);
        v.x = v.x * invn - 1e-5f; v.y = v.y * invn - 1e-5f;
        v.z = v.z * invn - 1e-5f; v.w = v.w * invn - 1e-5f;
        float s2 = fmaf(v.x, v.x, fmaf(v.y, v.y, fmaf(v.z, v.z, v.w * v.w)));
#pragma unroll
        for (int o = 16; o > 0; o >>= 1) s2 += __shfl_down_sync(0xffffffffu, s2, o);
        __syncthreads();
        if ((tid & 31) == 0) red[tid >> 5] = s2;
        __syncthreads();
        tot = red[0] + red[1] + red[2] + red[3];
    }

    __nv_bfloat162 p0 = __floats2bfloat162_rn(v.x, v.y);
    __nv_bfloat162 p1 = __floats2bfloat162_rn(v.z, v.w);
    uint2 u;
    u.x = *(uint32_t*)&p0;
    u.y = *(uint32_t*)&p1;
    ((uint2*)(g_xb + (size_t)row * DDIM))[tid] = u;
    if (tid == 0) {
        g_sq[row]  = tot;
        g_inv[row] = 1.f / (1.f - tot);
    }
}

// ------------------------------------------------------------- helpers ----
__device__ __forceinline__ void cp_async16(uint32_t dst, const void* src) {
    asm volatile("cp.async.cg.shared.global [%0], [%1], 16;\n" :: "r"(dst), "l"(src));
}
__device__ __forceinline__ void cp_commit() {
    asm volatile("cp.async.commit_group;\n" ::);
}
template <int N>
__device__ __forceinline__ void cp_wait() {
    asm volatile("cp.async.wait_group %0;\n" :: "n"(N));
}
__device__ __forceinline__ void ldsm_x4(uint32_t& r0, uint32_t& r1,
                                        uint32_t& r2, uint32_t& r3, uint32_t a) {
    asm volatile("ldmatrix.sync.aligned.m8n8.x4.shared.b16 {%0,%1,%2,%3}, [%4];\n"
                 : "=r"(r0), "=r"(r1), "=r"(r2), "=r"(r3) : "r"(a));
}

__device__ __forceinline__ float hyp_dist(float gv, float sa, float sb,
                                          float ia, float ib, bool diag) {
    float d2 = fmaxf(sa + sb - 2.f * gv, 0.f);
    float dn;
    asm("sqrt.approx.f32 %0, %1;" : "=f"(dn) : "f"(d2));
    float t = 2.f * dn * ia * ib;           // arg = 1 + t
    float w;
    asm("sqrt.approx.f32 %0, %1;" : "=f"(w) : "f"(t * (t + 2.f)));  // sqrt(arg^2-1)
    float arg = 1.f + t + w;
    float lg;
    asm("lg2.approx.f32 %0, %1;" : "=f"(lg) : "f"(arg));
    return (t > 0.f && !diag) ? lg * 0.69314718055994531f : 0.f;
}

// ---------------------------------------------------------------- gemm ----
__global__ void __launch_bounds__(512, 1)
gram_dist_kernel(float* __restrict__ out) {
    extern __shared__ char smem_raw[];
    __shared__ float s_sqi[128], s_invi[128], s_sqj[256], s_invj[256];

    const int b  = blockIdx.y;
    const int bN = b * NPTS;

    // block -> (ti, tj0); covers j-tiles tj0, tj0+1
    int p = blockIdx.x, ti = 0;
    while (p >= ((NT + 1 - ti) >> 1)) { p -= (NT + 1 - ti) >> 1; ++ti; }
    const int tj0 = ti + 2 * p;
    const bool valid1 = (tj0 + 1) < NT;

    const int tid  = threadIdx.x;
    const int warp = tid >> 5;
    const int lane = tid & 31;
    const int g  = lane >> 2;
    const int t2 = (lane & 3) * 2;
    const int wm = warp & 3;            // m quarter (32 rows)
    const int wn = warp >> 2;           // n quarter (64 of 256 cols)

    const uint32_t base_gen = (uint32_t)__cvta_generic_to_shared(smem_raw);
    const uint32_t sbase0   = (base_gen + 1023u) & ~1023u;
    float* stageT = (float*)(smem_raw + (sbase0 - base_gen));

    // epilogue params
    if (tid < 128) {
        s_sqi[tid]  = g_sq[bN + ti * 128 + tid];
        s_invi[tid] = g_inv[bN + ti * 128 + tid];
    } else if (tid < 384) {
        int u = tid - 128;
        int jr = tj0 * 128 + u;
        if (jr >= NPTS) jr -= 128;
        s_sqj[u]  = g_sq[bN + jr];
        s_invj[u] = g_inv[bN + jr];
    }

    // --- loader: rows 0..127 = A (ti), 128..383 = B (tj0..tj0+1) ---
    auto load_stage = [&](int s, int k0) {
        uint32_t sb = sbase0 + (uint32_t)s * STAGE_BYTES;
#pragma unroll
        for (int i = 0; i < 6; ++i) {
            int chunk = i * 512 + tid;
            int row = chunk >> 3;          // 0..383
            int c   = chunk & 7;
            int gr  = (row < 128) ? (ti * 128 + row) : (tj0 * 128 + row - 128);
            if (gr >= NPTS) gr -= 128;     // clamp invalid B1 rows
            const __nv_bfloat16* src = g_xb + (size_t)(bN + gr) * DDIM + (k0 + c * 8);
            uint32_t dst = sb + (uint32_t)(row * 128 + (((c ^ row) & 7) << 4));
            cp_async16(dst, src);
        }
    };

    // fragment geometry
    const int swz = lane & 7;
    const int dcA = lane >> 4;
    const int dcB = (lane >> 3) & 1;
    uint32_t aByte[2], bByte[4];
#pragma unroll
    for (int mt = 0; mt < 2; ++mt)
        aByte[mt] = (uint32_t)((wm * 32 + mt * 16 + (lane & 15)) * 128);
#pragma unroll
    for (int pp = 0; pp < 4; ++pp)
        bByte[pp] = (uint32_t)(16384 + (wn * 64 + pp * 16 + (lane & 7) + ((lane >> 4) << 3)) * 128);

    float acc[2][8][4];
#pragma unroll
    for (int a = 0; a < 2; ++a)
#pragma unroll
        for (int c = 0; c < 8; ++c)
#pragma unroll
            for (int r = 0; r < 4; ++r) acc[a][c][r] = 0.f;

    load_stage(0, 0);      cp_commit();
    load_stage(1, BK);     cp_commit();
    load_stage(2, 2 * BK); cp_commit();

    for (int kb = 0; kb < NCHUNK; ++kb) {
        if (kb < NCHUNK - 2)      cp_wait<2>();
        else if (kb == NCHUNK - 2) cp_wait<1>();
        else                       cp_wait<0>();
        __syncthreads();
        if (kb + 3 < NCHUNK) { load_stage((kb + 3) % NSTAGE, (kb + 3) * BK); cp_commit(); }

        uint32_t sb = sbase0 + (uint32_t)(kb % NSTAGE) * STAGE_BYTES;
#pragma unroll
        for (int kk = 0; kk < BK; kk += 16) {
            const int c0 = kk >> 3;
            const uint32_t cA = (uint32_t)(((c0 | dcA) ^ swz) << 4);
            const uint32_t cB = (uint32_t)(((c0 | dcB) ^ swz) << 4);
            uint32_t afr[2][4], bfr[8][2];
#pragma unroll
            for (int mt = 0; mt < 2; ++mt)
                ldsm_x4(afr[mt][0], afr[mt][1], afr[mt][2], afr[mt][3],
                        sb + aByte[mt] + cA);
#pragma unroll
            for (int pp = 0; pp < 4; ++pp)
                ldsm_x4(bfr[2 * pp][0], bfr[2 * pp][1], bfr[2 * pp + 1][0], bfr[2 * pp + 1][1],
                        sb + bByte[pp] + cB);
#pragma unroll
            for (int mt = 0; mt < 2; ++mt)
#pragma unroll
                for (int nt = 0; nt < 8; ++nt) {
                    asm volatile(
                        "mma.sync.aligned.m16n8k16.row.col.f32.bf16.bf16.f32 "
                        "{%0,%1,%2,%3}, {%4,%5,%6,%7}, {%8,%9}, {%0,%1,%2,%3};\n"
                        : "+f"(acc[mt][nt][0]), "+f"(acc[mt][nt][1]),
                          "+f"(acc[mt][nt][2]), "+f"(acc[mt][nt][3])
                        : "r"(afr[mt][0]), "r"(afr[mt][1]),
                          "r"(afr[mt][2]), "r"(afr[mt][3]),
                          "r"(bfr[nt][0]), "r"(bfr[nt][1]));
                }
        }
    }

    // ---------------- epilogue 1: distances + direct stores ---------------
    float* outB = out + (size_t)b * NPTS * NPTS;
    const uint32_t gi0 = (uint32_t)(ti * 128);
    const uint32_t gj0 = (uint32_t)(tj0 * 128);

#pragma unroll
    for (int mt = 0; mt < 2; ++mt) {
        const int rl = wm * 32 + mt * 16 + g;
#pragma unroll
        for (int nt = 0; nt < 8; ++nt) {
            const int cl = wn * 64 + nt * 8 + t2;     // 0..255
            const bool okst = (cl < 128) || valid1;
            const uint32_t gj = gj0 + (uint32_t)cl;
            const float sb0 = s_sqj[cl],     ib0 = s_invj[cl];
            const float sb1 = s_sqj[cl + 1], ib1 = s_invj[cl + 1];
#pragma unroll
            for (int h = 0; h < 2; ++h) {
                const uint32_t gi = gi0 + (uint32_t)(rl + h * 8);
                const float sa = s_sqi[rl + h * 8], ia = s_invi[rl + h * 8];
                float v0 = hyp_dist(acc[mt][nt][h * 2 + 0], sa, sb0, ia, ib0, gi == gj);
                float v1 = hyp_dist(acc[mt][nt][h * 2 + 1], sa, sb1, ia, ib1, gi == gj + 1u);
                acc[mt][nt][h * 2 + 0] = v0;
                acc[mt][nt][h * 2 + 1] = v1;
                if (okst) {
                    float2 pk; pk.x = v0; pk.y = v1;
                    *(float2*)(outB + (gi * (uint32_t)NPTS + gj)) = pk;
                }
            }
        }
    }

    // ---------------- epilogue 2: mirror via smem (4 groups x 2 passes) ----
    __syncthreads();                    // stage smem free for reuse
    const int itw = wn >> 1;            // pass in which this warp writes
    const int qb0 = (wn & 1) * 2;

    for (int it2 = 0; it2 < 2; ++it2) {
        if (it2 == itw) {
#pragma unroll
            for (int mt = 0; mt < 2; ++mt)
#pragma unroll
                for (int nt = 0; nt < 8; ++nt) {
                    const int qb = qb0 + (nt >> 2);
                    const int c  = (nt & 3) * 8 + t2;
                    float* tp = stageT + qb * 4224 + c * 132;
#pragma unroll
                    for (int h = 0; h < 2; ++h) {
                        const int r = wm * 32 + mt * 16 + g + h * 8;
                        tp[r]       = acc[mt][nt][h * 2 + 0];
                        tp[132 + r] = acc[mt][nt][h * 2 + 1];
                    }
                }
        }
        __syncthreads();
#pragma unroll
        for (int i2 = 0; i2 < 8; ++i2) {
            const int idx = i2 * 512 + tid;
            const int qb  = idx >> 10;
            const int jc  = it2 * 4 + qb;
            const int tjs = tj0 + (jc >> 2);
            if ((tjs > ti) && ((jc < 4) || valid1)) {
                const int rem  = idx & 1023;
                const int rowq = rem >> 5;
                const int q4   = rem & 31;
                float4 v = *(const float4*)(stageT + qb * 4224 + rowq * 132 + q4 * 4);
                const uint32_t gj = (uint32_t)(tjs * 128 + (jc & 3) * 32 + rowq);
                *(float4*)(outB + (gj * (uint32_t)NPTS + gi0 + (uint32_t)(q4 * 4))) = v;
            }
        }
        __syncthreads();
    }
}

// -------------------------------------------------------------- launch ----
extern "C" void kernel_launch(void* const* d_in, const int* in_sizes, int n_in,
                              void* d_out, int out_size) {
    const float* emb = (const float*)d_in[0];
    float* out = (float*)d_out;

    prep_kernel<<<BATCH * NPTS, 128>>>(emb);

    cudaFuncSetAttribute(gram_dist_kernel,
                         cudaFuncAttributeMaxDynamicSharedMemorySize, SMEM_DYN);
    dim3 grid(GRID_X, BATCH);
    gram_dist_kernel<<<grid, 512, SMEM_DYN>>>(out);
}